// round 9
// baseline (speedup 1.0000x reference)
#include <cuda_runtime.h>
#include <cuda_fp16.h>
#include <cstdint>

// ---------------- scratch ----------------
static __device__ __half g_hT16[512u * 8192u];         // 8 MB h^T in fp16 (bias added)

// XOR swizzle: 16B chunk index (bits[6:4]) ^= row%8 (bits[9:7])
#define SWZ(o) ((o) ^ (((o) >> 3) & 0x70))

__device__ __forceinline__ uint32_t smem_u32(const void* p){
    uint32_t a;
    asm("{ .reg .u64 t; cvta.to.shared.u64 t, %1; cvt.u32.u64 %0, t; }" : "=r"(a) : "l"(p));
    return a;
}
__device__ __forceinline__ void cp_async16(uint32_t dst, const void* src){
    asm volatile("cp.async.cg.shared.global [%0], [%1], 16;" :: "r"(dst), "l"(src) : "memory");
}
__device__ __forceinline__ void cp_commit(){ asm volatile("cp.async.commit_group;" ::: "memory"); }
template<int N> __device__ __forceinline__ void cp_wait(){
    asm volatile("cp.async.wait_group %0;" :: "n"(N) : "memory");
}
__device__ __forceinline__ uint32_t cvt_tf32(uint32_t bits){
    uint32_t r;
    asm("cvt.rna.tf32.f32 %0, %1;" : "=r"(r) : "f"(__uint_as_float(bits)));
    return r;
}
__device__ __forceinline__ void ldsm4(uint32_t& r0, uint32_t& r1, uint32_t& r2, uint32_t& r3,
                                      uint32_t addr){
    asm volatile("ldmatrix.sync.aligned.m8n8.x4.shared.b16 {%0,%1,%2,%3}, [%4];"
                 : "=r"(r0), "=r"(r1), "=r"(r2), "=r"(r3) : "r"(addr));
}
__device__ __forceinline__ void mma_tf32(float* c, const uint32_t* a, const uint32_t* b){
    asm volatile(
        "mma.sync.aligned.m16n8k8.row.col.f32.tf32.tf32.f32 "
        "{%0,%1,%2,%3}, {%4,%5,%6,%7}, {%8,%9}, {%0,%1,%2,%3};"
        : "+f"(c[0]), "+f"(c[1]), "+f"(c[2]), "+f"(c[3])
        : "r"(a[0]), "r"(a[1]), "r"(a[2]), "r"(a[3]), "r"(b[0]), "r"(b[1]));
}
__device__ __forceinline__ void mma_f16(float* c, const uint32_t* a, const uint32_t* b){
    asm volatile(
        "mma.sync.aligned.m16n8k16.row.col.f32.f16.f16.f32 "
        "{%0,%1,%2,%3}, {%4,%5,%6,%7}, {%8,%9}, {%0,%1,%2,%3};"
        : "+f"(c[0]), "+f"(c[1]), "+f"(c[2]), "+f"(c[3])
        : "r"(a[0]), "r"(a[1]), "r"(a[2]), "r"(a[3]), "r"(b[0]), "r"(b[1]));
}
// pack 8 fp32 (two float4) -> 16B of fp16 and store to smem
__device__ __forceinline__ void sts_f16x8(uint32_t dst, const float4& u, const float4& v){
    const __half2 h0 = __floats2half2_rn(u.x, u.y);
    const __half2 h1 = __floats2half2_rn(u.z, u.w);
    const __half2 h2 = __floats2half2_rn(v.x, v.y);
    const __half2 h3 = __floats2half2_rn(v.z, v.w);
    asm volatile("st.shared.v4.b32 [%0], {%1,%2,%3,%4};"
                 :: "r"(dst),
                    "r"(*(const uint32_t*)&h0), "r"(*(const uint32_t*)&h1),
                    "r"(*(const uint32_t*)&h2), "r"(*(const uint32_t*)&h3) : "memory");
}

// ================= GEMM1: tf32, fp16 output =================
// hT16[m][n] = half(sum_k A[m][k]*B[n][k] + bias[m]); A=W [512,512], B=input [8192,512]
#define G1_THREADS 256
#define G1_STAGE 49152
__global__ void __launch_bounds__(G1_THREADS, 1)
gemm1_tf32(const float* __restrict__ A, const float* __restrict__ B,
           const float* __restrict__ bias, __half* __restrict__ C,
           int ldA, int ldB, int ldC, int kiters)
{
    extern __shared__ char smem[];
    const uint32_t sb = smem_u32(smem);
    const int tid  = threadIdx.x;
    const int wid  = tid >> 5;
    const int lane = tid & 31;
    const int warp_m = wid & 1;
    const int warp_n = wid >> 1;
    const long m0 = (long)blockIdx.y * 128;
    const long n0 = (long)blockIdx.x * 256;

    float acc[4][8][4];
    #pragma unroll
    for (int i = 0; i < 4; i++)
        #pragma unroll
        for (int j = 0; j < 8; j++)
            #pragma unroll
            for (int k = 0; k < 4; k++) acc[i][j][k] = 0.0f;

    const int prow = tid >> 3;
    const int pc   = (tid & 7) * 16;

    auto copy_chunk = [&](long k0, uint32_t base, int j){
        if (j < 4){
            const int row = prow + j * 32;
            cp_async16(base + SWZ(row * 128 + pc),
                       A + (m0 + row) * (long)ldA + k0 + (pc >> 2));
        } else {
            const int row = prow + (j - 4) * 32;
            cp_async16(base + 16384u + SWZ(row * 128 + pc),
                       B + (n0 + row) * (long)ldB + k0 + (pc >> 2));
        }
    };

    const int rA  = (lane & 7) + ((lane >> 3) & 1) * 8;
    const int cbA = ((lane >> 4) & 1) * 16;
    const int rB  = (lane & 7) + ((lane >> 4) & 1) * 8;
    const int cbB = ((lane >> 3) & 1) * 16;

    auto compute = [&](int s, long k0n, uint32_t basen, bool do_copy){
        const uint32_t baseA = sb + (uint32_t)s * G1_STAGE;
        const uint32_t baseB = baseA + 16384u;
        uint32_t a[2][16], b[2][16];

        #pragma unroll
        for (int mt = 0; mt < 4; mt++){
            const int row = warp_m * 64 + mt * 16 + rA;
            ldsm4(a[0][mt*4+0], a[0][mt*4+1], a[0][mt*4+2], a[0][mt*4+3],
                  baseA + SWZ(row * 128 + cbA));
        }
        #pragma unroll
        for (int p = 0; p < 4; p++){
            const int row = warp_n * 64 + p * 16 + rB;
            ldsm4(b[0][p*4+0], b[0][p*4+1], b[0][p*4+2], b[0][p*4+3],
                  baseB + SWZ(row * 128 + cbB));
        }
        #pragma unroll
        for (int ks = 0; ks < 4; ks++){
            const int cur = ks & 1;
            const int nxt = cur ^ 1;
            const int kcn = (ks + 1) * 32;
            #pragma unroll
            for (int j = 0; j < 16; j++) b[cur][j] = cvt_tf32(b[cur][j]);
            #pragma unroll
            for (int mt = 0; mt < 4; mt++){
                if (ks < 3){
                    const int rowA = warp_m * 64 + mt * 16 + rA;
                    ldsm4(a[nxt][mt*4+0], a[nxt][mt*4+1], a[nxt][mt*4+2], a[nxt][mt*4+3],
                          baseA + SWZ(rowA * 128 + kcn + cbA));
                    const int rowB = warp_n * 64 + mt * 16 + rB;
                    ldsm4(b[nxt][mt*4+0], b[nxt][mt*4+1], b[nxt][mt*4+2], b[nxt][mt*4+3],
                          baseB + SWZ(rowB * 128 + kcn + cbB));
                }
                #pragma unroll
                for (int j = 0; j < 4; j++) a[cur][mt*4+j] = cvt_tf32(a[cur][mt*4+j]);
                #pragma unroll
                for (int nt = 0; nt < 8; nt++)
                    mma_tf32(acc[mt][nt], &a[cur][mt * 4],
                             &b[cur][(nt >> 1) * 4 + (nt & 1) * 2]);
            }
            if (do_copy){
                copy_chunk(k0n, basen, 3 * ks + 0);
                copy_chunk(k0n, basen, 3 * ks + 1);
                copy_chunk(k0n, basen, 3 * ks + 2);
            }
        }
    };

    #pragma unroll
    for (int s = 0; s < 3; s++){
        for (int j = 0; j < 12; j++)
            copy_chunk((long)s * 32, sb + (uint32_t)s * G1_STAGE, j);
        cp_commit();
    }
    for (int i = 0; i < kiters; i++){
        cp_wait<2>();
        __syncthreads();
        const bool dc = (i + 3 < kiters);
        compute(i & 3, (long)(i + 3) * 32,
                sb + (uint32_t)((i + 3) & 3) * G1_STAGE, dc);
        cp_commit();
    }

    const int gid = lane >> 2, tig = lane & 3;
    #pragma unroll
    for (int mt = 0; mt < 4; mt++){
        const long r0 = m0 + warp_m * 64 + mt * 16 + gid;
        const long r1 = r0 + 8;
        const float bv0 = __ldg(bias + r0);
        const float bv1 = __ldg(bias + r1);
        #pragma unroll
        for (int nt = 0; nt < 8; nt++){
            const long col = n0 + warp_n * 64 + nt * 8 + 2 * tig;
            const __half2 h0 = __floats2half2_rn(acc[mt][nt][0] + bv0, acc[mt][nt][1] + bv0);
            const __half2 h1 = __floats2half2_rn(acc[mt][nt][2] + bv1, acc[mt][nt][3] + bv1);
            *(__half2*)(C + r0 * ldC + col) = h0;
            *(__half2*)(C + r1 * ldC + col) = h1;
        }
    }
}

// ================= GEMM2: A fp32 (fused rn convert), B fp16, fp32 out =====
// out[m][n] = sum_k half(A[m][k]) * B16[n][k]; A=adj fp32 [8192,8192], B16=hT16 [512,8192]
#define G2_THREADS 256
#define G2_KTILE 64          // fp16 elements per tile: 128B smem rows
#define G2_STAGE 49152       // A 16KB (fp16) + B 32KB (fp16)
__global__ void __launch_bounds__(G2_THREADS, 1)
gemm2_f16(const float* __restrict__ A, const __half* __restrict__ B,
          float* __restrict__ C, long ldA, int ldB, int ldC, int kiters)
{
    extern __shared__ char smem[];
    const uint32_t sb = smem_u32(smem);
    const int tid  = threadIdx.x;
    const int wid  = tid >> 5;
    const int lane = tid & 31;
    const int warp_m = wid & 1;       // 2 M-groups of 64
    const int warp_n = wid >> 1;      // 4 N-groups of 64
    const long m0 = (long)blockIdx.y * 128;
    const long n0 = (long)blockIdx.x * 256;

    float acc[4][8][4];
    #pragma unroll
    for (int i = 0; i < 4; i++)
        #pragma unroll
        for (int j = 0; j < 8; j++)
            #pragma unroll
            for (int k = 0; k < 4; k++) acc[i][j][k] = 0.0f;

    // ---- B producer (cp.async, fp16): 256 rows x 128B, 8 chunks/thread ----
    const int prow = tid >> 3;          // 0..31
    const int pc   = (tid & 7) * 16;    // byte chunk in 128B row

    auto copy_b = [&](long k0, uint32_t base, int j){
        const int row = prow + j * 32;                 // B: 256 rows
        cp_async16(base + 16384u + SWZ(row * 128 + pc),
                   B + (n0 + row) * (long)ldB + k0 + (pc >> 1));
    };

    // ---- A producer (LDG fp32 -> rn fp16 -> STS): 128 rows x 128B fp16 ----
    // thread t: row = t>>1 (0..127), half = t&1 covers fp16 cols half*32..+31
    const int arow  = tid >> 1;
    const int ahalf = tid & 1;
    const float* aptr_base = A + (m0 + arow) * ldA + ahalf * 32;

    // ---- ldmatrix lane geometry (validated) ----
    const int rA  = (lane & 7) + ((lane >> 3) & 1) * 8;
    const int cbA = ((lane >> 4) & 1) * 16;
    const int rB  = (lane & 7) + ((lane >> 4) & 1) * 8;
    const int cbB = ((lane >> 3) & 1) * 16;

    auto compute = [&](int s, long k0n, uint32_t basen, bool do_copy){
        const uint32_t baseA = sb + (uint32_t)s * G2_STAGE;
        const uint32_t baseB = baseA + 16384u;
        const float* ap = aptr_base + k0n;
        uint32_t a[2][16], b[2][16];
        float4 v[8];

        // kstep 0 fragments (each kstep = 16 fp16 k = 32 bytes)
        #pragma unroll
        for (int mt = 0; mt < 4; mt++){
            const int row = warp_m * 64 + mt * 16 + rA;
            ldsm4(a[0][mt*4+0], a[0][mt*4+1], a[0][mt*4+2], a[0][mt*4+3],
                  baseA + SWZ(row * 128 + cbA));
        }
        #pragma unroll
        for (int p = 0; p < 4; p++){
            const int row = warp_n * 64 + p * 16 + rB;
            ldsm4(b[0][p*4+0], b[0][p*4+1], b[0][p*4+2], b[0][p*4+3],
                  baseB + SWZ(row * 128 + cbB));
        }

        #pragma unroll
        for (int ks = 0; ks < 4; ks++){
            const int cur = ks & 1;
            const int nxt = cur ^ 1;
            const int kcn = (ks + 1) * 32;
            #pragma unroll
            for (int mt = 0; mt < 4; mt++){
                if (ks < 3){
                    const int rowA = warp_m * 64 + mt * 16 + rA;
                    ldsm4(a[nxt][mt*4+0], a[nxt][mt*4+1], a[nxt][mt*4+2], a[nxt][mt*4+3],
                          baseA + SWZ(rowA * 128 + kcn + cbA));
                    const int rowB = warp_n * 64 + mt * 16 + rB;
                    ldsm4(b[nxt][mt*4+0], b[nxt][mt*4+1], b[nxt][mt*4+2], b[nxt][mt*4+3],
                          baseB + SWZ(rowB * 128 + kcn + cbB));
                }
                #pragma unroll
                for (int nt = 0; nt < 8; nt++)
                    mma_f16(acc[mt][nt], &a[cur][mt * 4],
                            &b[cur][(nt >> 1) * 4 + (nt & 1) * 2]);
            }
            if (do_copy){
                // A: phase the fp32 LDGs and fp16 STS across k-steps
                if (ks == 0){
                    #pragma unroll
                    for (int p = 0; p < 4; p++) v[p] = __ldg((const float4*)(ap) + p);
                } else if (ks == 1){
                    #pragma unroll
                    for (int p = 4; p < 8; p++) v[p] = __ldg((const float4*)(ap) + p);
                } else if (ks == 2){
                    sts_f16x8(basen + SWZ(arow * 128 + ahalf * 64 + 0),  v[0], v[1]);
                    sts_f16x8(basen + SWZ(arow * 128 + ahalf * 64 + 16), v[2], v[3]);
                } else {
                    sts_f16x8(basen + SWZ(arow * 128 + ahalf * 64 + 32), v[4], v[5]);
                    sts_f16x8(basen + SWZ(arow * 128 + ahalf * 64 + 48), v[6], v[7]);
                }
                // B: 2 cp.async chunks per k-step
                copy_b(k0n, basen, 2 * ks + 0);
                copy_b(k0n, basen, 2 * ks + 1);
            }
        }
    };

    // prologue: fill stages 0..2 (A synchronously, B via cp.async)
    #pragma unroll
    for (int s = 0; s < 3; s++){
        const long k0 = (long)s * G2_KTILE;
        const uint32_t base = sb + (uint32_t)s * G2_STAGE;
        const float* ap = aptr_base + k0;
        float4 u0, u1;
        #pragma unroll
        for (int c = 0; c < 4; c++){
            u0 = __ldg((const float4*)(ap) + 2 * c);
            u1 = __ldg((const float4*)(ap) + 2 * c + 1);
            sts_f16x8(base + SWZ(arow * 128 + ahalf * 64 + c * 16), u0, u1);
        }
        for (int j = 0; j < 8; j++) copy_b(k0, base, j);
        cp_commit();
    }

    for (int i = 0; i < kiters; i++){
        cp_wait<2>();
        __syncthreads();
        const bool dc = (i + 3 < kiters);
        compute(i & 3, (long)(i + 3) * G2_KTILE,
                sb + (uint32_t)((i + 3) & 3) * G2_STAGE, dc);
        cp_commit();
    }

    // epilogue (fp32 out)
    const int gid = lane >> 2, tig = lane & 3;
    #pragma unroll
    for (int mt = 0; mt < 4; mt++){
        const long r0 = m0 + warp_m * 64 + mt * 16 + gid;
        const long r1 = r0 + 8;
        #pragma unroll
        for (int nt = 0; nt < 8; nt++){
            const long col = n0 + warp_n * 64 + nt * 8 + 2 * tig;
            *(float2*)(C + r0 * ldC + col) = make_float2(acc[mt][nt][0], acc[mt][nt][1]);
            *(float2*)(C + r1 * ldC + col) = make_float2(acc[mt][nt][2], acc[mt][nt][3]);
        }
    }
}

// ---------------- launch ----------------
extern "C" void kernel_launch(void* const* d_in, const int* in_sizes, int n_in,
                              void* d_out, int out_size)
{
    const float* input = (const float*)d_in[0];   // [8192, 512]
    const float* adj   = (const float*)d_in[1];   // [8192, 8192]
    const float* W     = (const float*)d_in[2];   // [512, 512]
    const float* bias  = (const float*)d_in[3];   // [512]
    float* out = (float*)d_out;                   // [8192, 512]

    __half* hT16 = nullptr; cudaGetSymbolAddress((void**)&hT16, g_hT16);

    const int G1_SMEM = 4 * G1_STAGE;   // 196608
    const int G2_SMEM = 4 * G2_STAGE;   // 196608
    cudaFuncSetAttribute(gemm1_tf32, cudaFuncAttributeMaxDynamicSharedMemorySize, G1_SMEM);
    cudaFuncSetAttribute(gemm2_f16,  cudaFuncAttributeMaxDynamicSharedMemorySize, G2_SMEM);

    // 1) GEMM1 (tf32): hT16[o][n] = half(sum_i W[o][i]*input[n][i] + b[o])
    gemm1_tf32<<<dim3(8192 / 256, 512 / 128), G1_THREADS, G1_SMEM>>>(
        W, input, bias, hT16, 512, 512, 8192, 512 / 32);

    // 2) GEMM2 (fp16 MMA, fused A convert): out[m][o] = sum_k half(adj[m][k])*hT16[o][k]
    gemm2_f16<<<dim3(512 / 256, 8192 / 128), G2_THREADS, G2_SMEM>>>(
        adj, hT16, out, 8192L, 8192, 512, 8192 / G2_KTILE);
}

// round 10
// speedup vs baseline: 1.3431x; 1.3431x over previous
#include <cuda_runtime.h>
#include <cuda_fp16.h>
#include <cstdint>

// ---------------- scratch ----------------
static __device__ __half g_adj16[8192ull * 8192ull];   // 128 MB adj in fp16
static __device__ __half g_hT16[512u * 8192u];         // 8 MB  h^T in fp16 (bias added)

// XOR swizzle: 16B chunk index (bits[6:4]) ^= row%8 (bits[9:7])
#define SWZ(o) ((o) ^ (((o) >> 3) & 0x70))

__device__ __forceinline__ uint32_t smem_u32(const void* p){
    uint32_t a;
    asm("{ .reg .u64 t; cvta.to.shared.u64 t, %1; cvt.u32.u64 %0, t; }" : "=r"(a) : "l"(p));
    return a;
}
__device__ __forceinline__ void cp_async16(uint32_t dst, const void* src){
    asm volatile("cp.async.cg.shared.global [%0], [%1], 16;" :: "r"(dst), "l"(src) : "memory");
}
__device__ __forceinline__ void cp_commit(){ asm volatile("cp.async.commit_group;" ::: "memory"); }
template<int N> __device__ __forceinline__ void cp_wait(){
    asm volatile("cp.async.wait_group %0;" :: "n"(N) : "memory");
}
__device__ __forceinline__ uint32_t cvt_tf32(uint32_t bits){
    uint32_t r;
    asm("cvt.rna.tf32.f32 %0, %1;" : "=r"(r) : "f"(__uint_as_float(bits)));
    return r;
}
__device__ __forceinline__ void ldsm4(uint32_t& r0, uint32_t& r1, uint32_t& r2, uint32_t& r3,
                                      uint32_t addr){
    asm volatile("ldmatrix.sync.aligned.m8n8.x4.shared.b16 {%0,%1,%2,%3}, [%4];"
                 : "=r"(r0), "=r"(r1), "=r"(r2), "=r"(r3) : "r"(addr));
}
__device__ __forceinline__ void mma_tf32(float* c, const uint32_t* a, const uint32_t* b){
    asm volatile(
        "mma.sync.aligned.m16n8k8.row.col.f32.tf32.tf32.f32 "
        "{%0,%1,%2,%3}, {%4,%5,%6,%7}, {%8,%9}, {%0,%1,%2,%3};"
        : "+f"(c[0]), "+f"(c[1]), "+f"(c[2]), "+f"(c[3])
        : "r"(a[0]), "r"(a[1]), "r"(a[2]), "r"(a[3]), "r"(b[0]), "r"(b[1]));
}
__device__ __forceinline__ void mma_f16(float* c, const uint32_t* a, const uint32_t* b){
    asm volatile(
        "mma.sync.aligned.m16n8k16.row.col.f32.f16.f16.f32 "
        "{%0,%1,%2,%3}, {%4,%5,%6,%7}, {%8,%9}, {%0,%1,%2,%3};"
        : "+f"(c[0]), "+f"(c[1]), "+f"(c[2]), "+f"(c[3])
        : "r"(a[0]), "r"(a[1]), "r"(a[2]), "r"(a[3]), "r"(b[0]), "r"(b[1]));
}

// ================= convert: adj fp32 -> fp16 (rn), unrolled x4 =================
__global__ void __launch_bounds__(256)
cvt_f32_to_f16(const float4* __restrict__ src, uint2* __restrict__ dst, int n4)
{
    const int stride = gridDim.x * blockDim.x;
    int i = blockIdx.x * blockDim.x + threadIdx.x;
    // n4 is a multiple of 4*stride for our sizes (16777216 / 524288 = 32)
    for (; i + 3 * stride < n4; i += 4 * stride){
        float4 v0 = src[i];
        float4 v1 = src[i + stride];
        float4 v2 = src[i + 2 * stride];
        float4 v3 = src[i + 3 * stride];
        __half2 a0 = __floats2half2_rn(v0.x, v0.y), b0 = __floats2half2_rn(v0.z, v0.w);
        __half2 a1 = __floats2half2_rn(v1.x, v1.y), b1 = __floats2half2_rn(v1.z, v1.w);
        __half2 a2 = __floats2half2_rn(v2.x, v2.y), b2 = __floats2half2_rn(v2.z, v2.w);
        __half2 a3 = __floats2half2_rn(v3.x, v3.y), b3 = __floats2half2_rn(v3.z, v3.w);
        uint2 o0 = make_uint2(*(uint32_t*)&a0, *(uint32_t*)&b0);
        uint2 o1 = make_uint2(*(uint32_t*)&a1, *(uint32_t*)&b1);
        uint2 o2 = make_uint2(*(uint32_t*)&a2, *(uint32_t*)&b2);
        uint2 o3 = make_uint2(*(uint32_t*)&a3, *(uint32_t*)&b3);
        dst[i] = o0; dst[i + stride] = o1;
        dst[i + 2 * stride] = o2; dst[i + 3 * stride] = o3;
    }
    for (; i < n4; i += stride){
        float4 v = src[i];
        __half2 a = __floats2half2_rn(v.x, v.y), b = __floats2half2_rn(v.z, v.w);
        dst[i] = make_uint2(*(uint32_t*)&a, *(uint32_t*)&b);
    }
}

// ================= GEMM1: tf32, fp16 output =================
// hT16[m][n] = half(sum_k A[m][k]*B[n][k] + bias[m]); A=W [512,512], B=input [8192,512]
#define G1_THREADS 256
#define G1_STAGE 49152
__global__ void __launch_bounds__(G1_THREADS, 1)
gemm1_tf32(const float* __restrict__ A, const float* __restrict__ B,
           const float* __restrict__ bias, __half* __restrict__ C,
           int ldA, int ldB, int ldC, int kiters)
{
    extern __shared__ char smem[];
    const uint32_t sb = smem_u32(smem);
    const int tid  = threadIdx.x;
    const int wid  = tid >> 5;
    const int lane = tid & 31;
    const int warp_m = wid & 1;
    const int warp_n = wid >> 1;
    const long m0 = (long)blockIdx.y * 128;
    const long n0 = (long)blockIdx.x * 256;

    float acc[4][8][4];
    #pragma unroll
    for (int i = 0; i < 4; i++)
        #pragma unroll
        for (int j = 0; j < 8; j++)
            #pragma unroll
            for (int k = 0; k < 4; k++) acc[i][j][k] = 0.0f;

    const int prow = tid >> 3;
    const int pc   = (tid & 7) * 16;

    auto copy_chunk = [&](long k0, uint32_t base, int j){
        if (j < 4){
            const int row = prow + j * 32;
            cp_async16(base + SWZ(row * 128 + pc),
                       A + (m0 + row) * (long)ldA + k0 + (pc >> 2));
        } else {
            const int row = prow + (j - 4) * 32;
            cp_async16(base + 16384u + SWZ(row * 128 + pc),
                       B + (n0 + row) * (long)ldB + k0 + (pc >> 2));
        }
    };

    const int rA  = (lane & 7) + ((lane >> 3) & 1) * 8;
    const int cbA = ((lane >> 4) & 1) * 16;
    const int rB  = (lane & 7) + ((lane >> 4) & 1) * 8;
    const int cbB = ((lane >> 3) & 1) * 16;

    auto compute = [&](int s, long k0n, uint32_t basen, bool do_copy){
        const uint32_t baseA = sb + (uint32_t)s * G1_STAGE;
        const uint32_t baseB = baseA + 16384u;
        uint32_t a[2][16], b[2][16];

        #pragma unroll
        for (int mt = 0; mt < 4; mt++){
            const int row = warp_m * 64 + mt * 16 + rA;
            ldsm4(a[0][mt*4+0], a[0][mt*4+1], a[0][mt*4+2], a[0][mt*4+3],
                  baseA + SWZ(row * 128 + cbA));
        }
        #pragma unroll
        for (int p = 0; p < 4; p++){
            const int row = warp_n * 64 + p * 16 + rB;
            ldsm4(b[0][p*4+0], b[0][p*4+1], b[0][p*4+2], b[0][p*4+3],
                  baseB + SWZ(row * 128 + cbB));
        }
        #pragma unroll
        for (int ks = 0; ks < 4; ks++){
            const int cur = ks & 1;
            const int nxt = cur ^ 1;
            const int kcn = (ks + 1) * 32;
            #pragma unroll
            for (int j = 0; j < 16; j++) b[cur][j] = cvt_tf32(b[cur][j]);
            #pragma unroll
            for (int mt = 0; mt < 4; mt++){
                if (ks < 3){
                    const int rowA = warp_m * 64 + mt * 16 + rA;
                    ldsm4(a[nxt][mt*4+0], a[nxt][mt*4+1], a[nxt][mt*4+2], a[nxt][mt*4+3],
                          baseA + SWZ(rowA * 128 + kcn + cbA));
                    const int rowB = warp_n * 64 + mt * 16 + rB;
                    ldsm4(b[nxt][mt*4+0], b[nxt][mt*4+1], b[nxt][mt*4+2], b[nxt][mt*4+3],
                          baseB + SWZ(rowB * 128 + kcn + cbB));
                }
                #pragma unroll
                for (int j = 0; j < 4; j++) a[cur][mt*4+j] = cvt_tf32(a[cur][mt*4+j]);
                #pragma unroll
                for (int nt = 0; nt < 8; nt++)
                    mma_tf32(acc[mt][nt], &a[cur][mt * 4],
                             &b[cur][(nt >> 1) * 4 + (nt & 1) * 2]);
            }
            if (do_copy){
                copy_chunk(k0n, basen, 3 * ks + 0);
                copy_chunk(k0n, basen, 3 * ks + 1);
                copy_chunk(k0n, basen, 3 * ks + 2);
            }
        }
    };

    #pragma unroll
    for (int s = 0; s < 3; s++){
        for (int j = 0; j < 12; j++)
            copy_chunk((long)s * 32, sb + (uint32_t)s * G1_STAGE, j);
        cp_commit();
    }
    for (int i = 0; i < kiters; i++){
        cp_wait<2>();
        __syncthreads();
        const bool dc = (i + 3 < kiters);
        compute(i & 3, (long)(i + 3) * 32,
                sb + (uint32_t)((i + 3) & 3) * G1_STAGE, dc);
        cp_commit();
    }

    const int gid = lane >> 2, tig = lane & 3;
    #pragma unroll
    for (int mt = 0; mt < 4; mt++){
        const long r0 = m0 + warp_m * 64 + mt * 16 + gid;
        const long r1 = r0 + 8;
        const float bv0 = __ldg(bias + r0);
        const float bv1 = __ldg(bias + r1);
        #pragma unroll
        for (int nt = 0; nt < 8; nt++){
            const long col = n0 + warp_n * 64 + nt * 8 + 2 * tig;
            const __half2 h0 = __floats2half2_rn(acc[mt][nt][0] + bv0, acc[mt][nt][1] + bv0);
            const __half2 h1 = __floats2half2_rn(acc[mt][nt][2] + bv1, acc[mt][nt][3] + bv1);
            *(__half2*)(C + r0 * ldC + col) = h0;
            *(__half2*)(C + r1 * ldC + col) = h1;
        }
    }
}

// ================= GEMM2: fp16 inputs, fp32 out (validated R7) =================
// out[m][n] = sum_k A16[m][k] * B16[n][k]; A16=adj fp16 [8192,8192], B16=hT16 [512,8192]
#define G2_THREADS 256
#define G2_KTILE 64          // fp16 elements: 128B rows
#define G2_STAGE 49152       // A 16KB + B 32KB
__global__ void __launch_bounds__(G2_THREADS, 1)
gemm2_f16(const __half* __restrict__ A, const __half* __restrict__ B,
          float* __restrict__ C, int ldA, int ldB, int ldC, int kiters)
{
    extern __shared__ char smem[];
    const uint32_t sb = smem_u32(smem);
    const int tid  = threadIdx.x;
    const int wid  = tid >> 5;
    const int lane = tid & 31;
    const int warp_m = wid & 1;       // 2 M-groups of 64
    const int warp_n = wid >> 1;      // 4 N-groups of 64
    const long m0 = (long)blockIdx.y * 128;
    const long n0 = (long)blockIdx.x * 256;

    float acc[4][8][4];
    #pragma unroll
    for (int i = 0; i < 4; i++)
        #pragma unroll
        for (int j = 0; j < 8; j++)
            #pragma unroll
            for (int k = 0; k < 4; k++) acc[i][j][k] = 0.0f;

    const int prow = tid >> 3;          // 0..31
    const int pc   = (tid & 7) * 16;    // byte chunk in 128B row

    auto copy_chunk = [&](long k0, uint32_t base, int j){
        if (j < 4){
            const int row = prow + j * 32;                       // A: 128 rows
            cp_async16(base + SWZ(row * 128 + pc),
                       A + (m0 + row) * (long)ldA + k0 + (pc >> 1));
        } else {
            const int row = prow + (j - 4) * 32;                 // B: 256 rows
            cp_async16(base + 16384u + SWZ(row * 128 + pc),
                       B + (n0 + row) * (long)ldB + k0 + (pc >> 1));
        }
    };

    const int rA  = (lane & 7) + ((lane >> 3) & 1) * 8;
    const int cbA = ((lane >> 4) & 1) * 16;
    const int rB  = (lane & 7) + ((lane >> 4) & 1) * 8;
    const int cbB = ((lane >> 3) & 1) * 16;

    auto compute = [&](int s, long k0n, uint32_t basen, bool do_copy){
        const uint32_t baseA = sb + (uint32_t)s * G2_STAGE;
        const uint32_t baseB = baseA + 16384u;
        uint32_t a[2][16], b[2][16];

        #pragma unroll
        for (int mt = 0; mt < 4; mt++){
            const int row = warp_m * 64 + mt * 16 + rA;
            ldsm4(a[0][mt*4+0], a[0][mt*4+1], a[0][mt*4+2], a[0][mt*4+3],
                  baseA + SWZ(row * 128 + cbA));
        }
        #pragma unroll
        for (int p = 0; p < 4; p++){
            const int row = warp_n * 64 + p * 16 + rB;
            ldsm4(b[0][p*4+0], b[0][p*4+1], b[0][p*4+2], b[0][p*4+3],
                  baseB + SWZ(row * 128 + cbB));
        }

        #pragma unroll
        for (int ks = 0; ks < 4; ks++){
            const int cur = ks & 1;
            const int nxt = cur ^ 1;
            const int kcn = (ks + 1) * 32;
            #pragma unroll
            for (int mt = 0; mt < 4; mt++){
                if (ks < 3){
                    const int rowA = warp_m * 64 + mt * 16 + rA;
                    ldsm4(a[nxt][mt*4+0], a[nxt][mt*4+1], a[nxt][mt*4+2], a[nxt][mt*4+3],
                          baseA + SWZ(rowA * 128 + kcn + cbA));
                    const int rowB = warp_n * 64 + mt * 16 + rB;
                    ldsm4(b[nxt][mt*4+0], b[nxt][mt*4+1], b[nxt][mt*4+2], b[nxt][mt*4+3],
                          baseB + SWZ(rowB * 128 + kcn + cbB));
                }
                #pragma unroll
                for (int nt = 0; nt < 8; nt++)
                    mma_f16(acc[mt][nt], &a[cur][mt * 4],
                            &b[cur][(nt >> 1) * 4 + (nt & 1) * 2]);
            }
            if (do_copy){
                copy_chunk(k0n, basen, 3 * ks + 0);
                copy_chunk(k0n, basen, 3 * ks + 1);
                copy_chunk(k0n, basen, 3 * ks + 2);
            }
        }
    };

    #pragma unroll
    for (int s = 0; s < 3; s++){
        for (int j = 0; j < 12; j++)
            copy_chunk((long)s * G2_KTILE, sb + (uint32_t)s * G2_STAGE, j);
        cp_commit();
    }
    for (int i = 0; i < kiters; i++){
        cp_wait<2>();
        __syncthreads();
        const bool dc = (i + 3 < kiters);
        compute(i & 3, (long)(i + 3) * G2_KTILE,
                sb + (uint32_t)((i + 3) & 3) * G2_STAGE, dc);
        cp_commit();
    }

    const int gid = lane >> 2, tig = lane & 3;
    #pragma unroll
    for (int mt = 0; mt < 4; mt++){
        const long r0 = m0 + warp_m * 64 + mt * 16 + gid;
        const long r1 = r0 + 8;
        #pragma unroll
        for (int nt = 0; nt < 8; nt++){
            const long col = n0 + warp_n * 64 + nt * 8 + 2 * tig;
            *(float2*)(C + r0 * ldC + col) = make_float2(acc[mt][nt][0], acc[mt][nt][1]);
            *(float2*)(C + r1 * ldC + col) = make_float2(acc[mt][nt][2], acc[mt][nt][3]);
        }
    }
}

// ---------------- launch ----------------
extern "C" void kernel_launch(void* const* d_in, const int* in_sizes, int n_in,
                              void* d_out, int out_size)
{
    const float* input = (const float*)d_in[0];   // [8192, 512]
    const float* adj   = (const float*)d_in[1];   // [8192, 8192]
    const float* W     = (const float*)d_in[2];   // [512, 512]
    const float* bias  = (const float*)d_in[3];   // [512]
    float* out = (float*)d_out;                   // [8192, 512]

    __half* adj16 = nullptr; cudaGetSymbolAddress((void**)&adj16, g_adj16);
    __half* hT16  = nullptr; cudaGetSymbolAddress((void**)&hT16,  g_hT16);

    const int G1_SMEM = 4 * G1_STAGE;   // 196608
    const int G2_SMEM = 4 * G2_STAGE;   // 196608
    cudaFuncSetAttribute(gemm1_tf32, cudaFuncAttributeMaxDynamicSharedMemorySize, G1_SMEM);
    cudaFuncSetAttribute(gemm2_f16,  cudaFuncAttributeMaxDynamicSharedMemorySize, G2_SMEM);

    // Fork a side stream so GEMM1 (tensor-bound, ~15us) overlaps the
    // DRAM-bound adj convert (~55us). Stream/event objects are host-side;
    // graph capture records the cross-stream dependencies as graph edges.
    cudaStream_t s2;
    cudaStreamCreateWithFlags(&s2, cudaStreamNonBlocking);
    cudaEvent_t eFork, eJoin;
    cudaEventCreateWithFlags(&eFork, cudaEventDisableTiming);
    cudaEventCreateWithFlags(&eJoin, cudaEventDisableTiming);

    cudaEventRecord(eFork, 0);
    cudaStreamWaitEvent(s2, eFork, 0);

    // side stream: GEMM1 (tf32): hT16[o][n] = half(sum_i W[o][i]*input[n][i] + b[o])
    gemm1_tf32<<<dim3(8192 / 256, 512 / 128), G1_THREADS, G1_SMEM, s2>>>(
        W, input, bias, hT16, 512, 512, 8192, 512 / 32);
    cudaEventRecord(eJoin, s2);

    // main stream: adj -> fp16 (rn)
    cvt_f32_to_f16<<<2048, 256>>>((const float4*)adj, (uint2*)adj16, 8192 * 8192 / 4);

    // join, then GEMM2 (fp16): out[m][o] = sum_k adj16[m][k]*hT16[o][k]
    cudaStreamWaitEvent(0, eJoin, 0);
    gemm2_f16<<<dim3(512 / 256, 8192 / 128), G2_THREADS, G2_SMEM>>>(
        adj16, hT16, out, 8192, 8192, 512, 8192 / G2_KTILE);

    cudaEventDestroy(eFork);
    cudaEventDestroy(eJoin);
    cudaStreamDestroy(s2);
}